// round 1
// baseline (speedup 1.0000x reference)
#include <cuda_runtime.h>

#define K2   49
#define DIMC 96
#define NH   3
#define NT   256

// ---- shared memory layout (floats) ----
#define XT_STR 52                    // padded x-transpose row stride
#define XT_OFF 0
#define XT_SZ  (DIMC * XT_STR)       // 4992
#define QKP    33                    // padded q/k row stride (odd -> conflict-free)
#define QS_OFF (XT_OFF + XT_SZ)
#define QS_SZ  (NH * K2 * QKP)       // 4851
#define KS_OFF (QS_OFF + QS_SZ)
#define S_OFF  (KS_OFF + QS_SZ)
#define S_SZ   (NH * K2 * K2)        // 7203
#define Y_OFF  (S_OFF + S_SZ)
#define Y_SZ   (K2 * DIMC)           // 4704
#define VT_OFF (Y_OFF + Y_SZ)
#define VT_SZ  (DIMC * K2)           // 4704
#define BOTT_OFF (VT_OFF + VT_SZ)
#define SMEM_FLOATS (BOTT_OFF + 64)  // 31369 floats = 125476 B

__global__ __launch_bounds__(NT, 1)
void gwa_kernel(const float* __restrict__ x,    const float* __restrict__ mask,
                const float* __restrict__ qk_w, const float* __restrict__ qk_b,
                const float* __restrict__ rpb,  const float* __restrict__ botw,
                const float* __restrict__ botb, const float* __restrict__ Gw,
                const float* __restrict__ Bw,   const float* __restrict__ pw,
                const float* __restrict__ pb,   const int*   __restrict__ rp,
                float* __restrict__ out, int nW)
{
    extern __shared__ float sm[];
    float* xT   = sm + XT_OFF;   // [96][52]  xT[c][j]
    float* qs   = sm + QS_OFF;   // [3][49][33]
    float* ks   = sm + KS_OFF;   // [3][49][33]
    float* S    = sm + S_OFF;    // [3][49][49]
    float* Y    = sm + Y_OFF;    // [49][96]
    float* VT   = sm + VT_OFF;   // [96][49]  VT[c][k]
    float* bott = sm + BOTT_OFF; // [49]

    const int b   = blockIdx.x;
    const int tid = threadIdx.x;
    const float* xg = x + (size_t)b * (K2 * DIMC);

    // ---------------- Phase 1: load x transposed ----------------
    for (int i = tid; i < K2 * DIMC; i += NT) {
        int j = i / DIMC, c = i - j * DIMC;
        xT[c * XT_STR + j] = xg[i];
    }
    __syncthreads();

    // bottleneck: bott[j] = x[j,:] . botw + botb
    if (tid < K2) {
        float acc = botb[0];
        #pragma unroll 4
        for (int c = 0; c < DIMC; c++) acc = fmaf(xT[c * XT_STR + tid], botw[c], acc);
        bott[tid] = acc;
    }

    // ---------------- Phase 2: fused Q/K/Y projection ----------------
    // Output rows r: [0,96)=Q (scaled), [96,192)=K, [192,288)=Y (weights = Gmat^T cols)
    // Tiles: 72 r-tiles (x4) * 7 j-tiles (x7) = 504 tiles
    const float SCALE = 0.17677669529663687f;  // 32^-0.5
    for (int t = tid; t < 72 * 7; t += NT) {
        const int r0 = (t / 7) * 4;
        const int j0 = (t % 7) * 7;

        float acc[4][7];
        const float* wp[4];
        int wstr;
        if (r0 < 192) {
            #pragma unroll
            for (int a = 0; a < 4; a++) {
                wp[a] = qk_w + (r0 + a) * 96;
                float bias = qk_b[r0 + a];
                #pragma unroll
                for (int u = 0; u < 7; u++) acc[a][u] = bias;
            }
            wstr = 1;
        } else {
            #pragma unroll
            for (int a = 0; a < 4; a++) {
                wp[a] = Gw + (r0 - 192 + a);
                #pragma unroll
                for (int u = 0; u < 7; u++) acc[a][u] = 0.f;
            }
            wstr = 96;
        }

        for (int c = 0; c < DIMC; c++) {
            float xv[7];
            #pragma unroll
            for (int u = 0; u < 7; u++) xv[u] = xT[c * XT_STR + j0 + u];
            float wv[4];
            #pragma unroll
            for (int a = 0; a < 4; a++) { wv[a] = *wp[a]; wp[a] += wstr; }
            #pragma unroll
            for (int a = 0; a < 4; a++)
                #pragma unroll
                for (int u = 0; u < 7; u++)
                    acc[a][u] = fmaf(wv[a], xv[u], acc[a][u]);
        }

        if (r0 < 96) {
            #pragma unroll
            for (int a = 0; a < 4; a++) {
                int r = r0 + a, h = r >> 5, e = r & 31;
                #pragma unroll
                for (int u = 0; u < 7; u++)
                    qs[h * (K2 * QKP) + (j0 + u) * QKP + e] = acc[a][u] * SCALE;
            }
        } else if (r0 < 192) {
            #pragma unroll
            for (int a = 0; a < 4; a++) {
                int r = r0 - 96 + a, h = r >> 5, e = r & 31;
                #pragma unroll
                for (int u = 0; u < 7; u++)
                    ks[h * (K2 * QKP) + (j0 + u) * QKP + e] = acc[a][u];
            }
        } else {
            int he0 = r0 - 192;
            #pragma unroll
            for (int a = 0; a < 4; a++)
                #pragma unroll
                for (int u = 0; u < 7; u++)
                    Y[(j0 + u) * DIMC + he0 + a] = acc[a][u];
        }
    }
    __syncthreads();

    // ---------------- Phase 3: attention logits ----------------
    const float* maskb = mask + (size_t)(b % nW) * (K2 * K2);
    for (int idx = tid; idx < NH * K2 * K2; idx += NT) {
        int h   = idx / (K2 * K2);
        int rem = idx - h * (K2 * K2);
        int i   = rem / K2;
        int j   = rem - i * K2;
        const float* qrow = qs + h * (K2 * QKP) + i * QKP;
        const float* krow = ks + h * (K2 * QKP) + j * QKP;
        float acc = 0.f;
        #pragma unroll
        for (int e = 0; e < 32; e++) acc = fmaf(qrow[e], krow[e], acc);
        int ri = rp[rem];
        acc += rpb[ri * NH + h] + maskb[rem];
        S[idx] = acc;
    }
    __syncthreads();

    // ---------------- Phase 4: softmax (warp per row) ----------------
    {
        int warp = tid >> 5, lane = tid & 31;
        for (int row = warp; row < NH * K2; row += NT / 32) {
            float* srow = S + row * K2;
            float v0 = srow[lane];
            float v1 = (lane < 17) ? srow[32 + lane] : -1e30f;
            float m = fmaxf(v0, v1);
            #pragma unroll
            for (int o = 16; o; o >>= 1) m = fmaxf(m, __shfl_xor_sync(~0u, m, o));
            float e0 = __expf(v0 - m);
            float e1 = (lane < 17) ? __expf(v1 - m) : 0.f;
            float s = e0 + e1;
            #pragma unroll
            for (int o = 16; o; o >>= 1) s += __shfl_xor_sync(~0u, s, o);
            float inv = __fdividef(1.f, s);
            srow[lane] = e0 * inv;
            if (lane < 17) srow[32 + lane] = e1 * inv;
        }
    }
    __syncthreads();

    // ---------------- Phase 5: Z = S @ Y, apply bott & B_w, store transposed ----------------
    for (int idx = tid; idx < NH * K2 * 32; idx += NT) {
        int h   = idx / (K2 * 32);
        int rem = idx - h * (K2 * 32);
        int i   = rem >> 5;
        int e   = rem & 31;
        int he  = h * 32 + e;
        const float* srow = S + h * (K2 * K2) + i * K2;
        float acc = 0.f;
        #pragma unroll 7
        for (int j = 0; j < K2; j++) acc = fmaf(srow[j], Y[j * DIMC + he], acc);
        VT[he * K2 + i] = bott[i] * (acc + Bw[he]);
    }
    __syncthreads();

    // ---------------- Phase 6: output projection ----------------
    float* og = out + (size_t)b * (K2 * DIMC);
    for (int t = tid; t < K2 * 24; t += NT) {
        int i  = t / 24;
        int d0 = (t - i * 24) * 4;
        const float* w0 = pw + (d0 + 0) * 96;
        const float* w1 = pw + (d0 + 1) * 96;
        const float* w2 = pw + (d0 + 2) * 96;
        const float* w3 = pw + (d0 + 3) * 96;
        float a0 = pb[d0 + 0], a1 = pb[d0 + 1], a2 = pb[d0 + 2], a3 = pb[d0 + 3];
        for (int c = 0; c < DIMC; c++) {
            float v = VT[c * K2 + i];
            a0 = fmaf(v, w0[c], a0);
            a1 = fmaf(v, w1[c], a1);
            a2 = fmaf(v, w2[c], a2);
            a3 = fmaf(v, w3[c], a3);
        }
        float4 res = make_float4(a0, a1, a2, a3);
        *reinterpret_cast<float4*>(og + i * DIMC + d0) = res;
    }
}

extern "C" void kernel_launch(void* const* d_in, const int* in_sizes, int n_in,
                              void* d_out, int out_size) {
    const float* x    = (const float*)d_in[0];
    const float* mask = (const float*)d_in[1];
    const float* qk_w = (const float*)d_in[2];
    const float* qk_b = (const float*)d_in[3];
    const float* rpb  = (const float*)d_in[4];
    const float* botw = (const float*)d_in[5];
    const float* botb = (const float*)d_in[6];
    const float* Gw   = (const float*)d_in[7];
    const float* Bw   = (const float*)d_in[8];
    const float* pw   = (const float*)d_in[9];
    const float* pb   = (const float*)d_in[10];
    const int*   rp   = (const int*)d_in[11];

    const int BW = in_sizes[0] / (K2 * DIMC);        // 128
    const int nW = in_sizes[1] / (K2 * K2);          // 64

    size_t smem = SMEM_FLOATS * sizeof(float);
    cudaFuncSetAttribute(gwa_kernel, cudaFuncAttributeMaxDynamicSharedMemorySize, (int)smem);
    gwa_kernel<<<BW, NT, smem>>>(x, mask, qk_w, qk_b, rpb, botw, botb,
                                 Gw, Bw, pw, pb, rp, (float*)d_out, nW);
}

// round 2
// speedup vs baseline: 3.6577x; 3.6577x over previous
#include <cuda_runtime.h>

#define K2   49
#define DIMC 96
#define NH   3
#define NT   512

// ---- shared memory layout (floats) ----
#define XS_STR  100
#define XS_OFF  0
#define GWT_OFF (XS_OFF + 52 * XS_STR)        // 5200
#define GWT_STR 100
#define P_OFF   (GWT_OFF + 96 * GWT_STR)      // 14800
#define P_STR   52
#define S_OFF   (P_OFF + 288 * P_STR)         // 29776
#define S_STR   52
#define V_OFF   (S_OFF + 147 * S_STR)         // 37420
#define V_STR   96
#define BOTT_OFF (V_OFF + 52 * V_STR)         // 42412
#define SMEM_FLOATS (BOTT_OFF + 64)           // 42476 floats = 169904 B

__device__ __forceinline__ float dot4(float4 a, float4 b, float acc) {
    acc = fmaf(a.x, b.x, acc);
    acc = fmaf(a.y, b.y, acc);
    acc = fmaf(a.z, b.z, acc);
    acc = fmaf(a.w, b.w, acc);
    return acc;
}

__global__ __launch_bounds__(NT, 1)
void gwa_kernel(const float* __restrict__ x,    const float* __restrict__ mask,
                const float* __restrict__ qk_w, const float* __restrict__ qk_b,
                const float* __restrict__ rpb,  const float* __restrict__ botw,
                const float* __restrict__ botb, const float* __restrict__ Gw,
                const float* __restrict__ Bw,   const float* __restrict__ pw,
                const float* __restrict__ pb,   const int*   __restrict__ rp,
                float* __restrict__ out, int nW)
{
    extern __shared__ float sm[];
    float* xs   = sm + XS_OFF;    // [52][100]  xs[j][c], rows 49..51 zero
    float* GwT  = sm + GWT_OFF;   // [96][100]  GwT[he][c]
    float* P    = sm + P_OFF;     // [288][52]  rows 0..95 Q(scaled), 96..191 K, 192..287 Y^T
    float* S    = sm + S_OFF;     // [147][52]  S[h*49+i][j], cols 49..51 zero
    float* V    = sm + V_OFF;     // [52][96]   V[i][he]
    float* bott = sm + BOTT_OFF;  // [49]

    const int b   = blockIdx.x;
    const int tid = threadIdx.x;

    // ---------------- Phase 1: stage x (row-major, padded), GwT, pads, bott ----------------
    {
        const float4* xg4 = (const float4*)(x + (size_t)b * (K2 * DIMC));
        for (int i = tid; i < K2 * DIMC / 4; i += NT) {       // 1176
            int j = i / 24, c4 = i - j * 24;
            *(float4*)&xs[j * XS_STR + c4 * 4] = xg4[i];
        }
        if (tid < 75) {                                       // zero xs rows 49..51
            int r = tid / 25, cc = tid - r * 25;
            *(float4*)&xs[(49 + r) * XS_STR + cc * 4] = make_float4(0.f, 0.f, 0.f, 0.f);
        }
        for (int i = tid; i < 96 * 96; i += NT) {             // GwT[he][c] = Gw[c*96+he]
            int c = i / 96, he = i - c * 96;
            GwT[he * GWT_STR + c] = Gw[i];
        }
        for (int i = tid; i < 288 * 3; i += NT)               // zero P pad cols 49..51
            P[(i / 3) * P_STR + 49 + (i % 3)] = 0.f;
        if (tid < 147 * 3)                                    // zero S pad cols 49..51
            S[(tid / 3) * S_STR + 49 + (tid % 3)] = 0.f;
        if (tid < K2) {                                       // bott from global x
            const float4* xr = (const float4*)(x + (size_t)b * (K2 * DIMC) + tid * DIMC);
            const float4* bw4 = (const float4*)botw;
            float acc = botb[0];
            #pragma unroll 6
            for (int c4 = 0; c4 < 24; c4++) acc = dot4(xr[c4], bw4[c4], acc);
            bott[tid] = acc;
        }
    }
    __syncthreads();

    // ---------------- Phase 2: fused Q/K/Y projection, 8r x 4j tiles (468 tiles) ----------------
    const float SCALE = 0.17677669529663687f;  // 32^-0.5
    if (tid < 468) {
        const int r0 = (tid / 13) * 8;
        const int j0 = (tid % 13) * 4;
        float acc[8][4];

        if (r0 < 192) {
            #pragma unroll
            for (int a = 0; a < 8; a++) {
                float bv = qk_b[r0 + a];
                #pragma unroll
                for (int u = 0; u < 4; u++) acc[a][u] = bv;
            }
            #pragma unroll 2
            for (int c0 = 0; c0 < DIMC; c0 += 4) {
                float4 xv[4];
                #pragma unroll
                for (int u = 0; u < 4; u++) xv[u] = *(const float4*)&xs[(j0 + u) * XS_STR + c0];
                #pragma unroll
                for (int a = 0; a < 8; a++) {
                    float4 wv = *(const float4*)&qk_w[(r0 + a) * 96 + c0];
                    #pragma unroll
                    for (int u = 0; u < 4; u++) acc[a][u] = dot4(wv, xv[u], acc[a][u]);
                }
            }
        } else {
            #pragma unroll
            for (int a = 0; a < 8; a++)
                #pragma unroll
                for (int u = 0; u < 4; u++) acc[a][u] = 0.f;
            #pragma unroll 2
            for (int c0 = 0; c0 < DIMC; c0 += 4) {
                float4 xv[4];
                #pragma unroll
                for (int u = 0; u < 4; u++) xv[u] = *(const float4*)&xs[(j0 + u) * XS_STR + c0];
                #pragma unroll
                for (int a = 0; a < 8; a++) {
                    float4 wv = *(const float4*)&GwT[(r0 - 192 + a) * GWT_STR + c0];
                    #pragma unroll
                    for (int u = 0; u < 4; u++) acc[a][u] = dot4(wv, xv[u], acc[a][u]);
                }
            }
        }

        const float s = (r0 < 96) ? SCALE : 1.f;
        if (j0 != 48) {
            #pragma unroll
            for (int a = 0; a < 8; a++) {
                float4 o = make_float4(acc[a][0] * s, acc[a][1] * s, acc[a][2] * s, acc[a][3] * s);
                *(float4*)&P[(r0 + a) * P_STR + j0] = o;
            }
        } else {
            #pragma unroll
            for (int a = 0; a < 8; a++) P[(r0 + a) * P_STR + 48] = acc[a][0] * s;
        }
    }
    __syncthreads();

    // ---------------- Phase 3: attention logits, 4i x 4j tiles (507 tiles) ----------------
    const float* maskb = mask + (size_t)(b % nW) * (K2 * K2);
    if (tid < 507) {
        const int h   = tid / 169;
        const int rem = tid - h * 169;
        const int i0  = (rem / 13) * 4;
        const int j0  = (rem % 13) * 4;
        const float* qbase = P + (h * 32) * P_STR + i0;
        const float* kbase = P + (96 + h * 32) * P_STR + j0;

        float acc[4][4];
        #pragma unroll
        for (int ii = 0; ii < 4; ii++)
            #pragma unroll
            for (int jj = 0; jj < 4; jj++) acc[ii][jj] = 0.f;

        #pragma unroll 4
        for (int e = 0; e < 32; e++) {
            float4 qv = *(const float4*)&qbase[e * P_STR];
            float4 kv = *(const float4*)&kbase[e * P_STR];
            float qa[4] = {qv.x, qv.y, qv.z, qv.w};
            float ka[4] = {kv.x, kv.y, kv.z, kv.w};
            #pragma unroll
            for (int ii = 0; ii < 4; ii++)
                #pragma unroll
                for (int jj = 0; jj < 4; jj++)
                    acc[ii][jj] = fmaf(qa[ii], ka[jj], acc[ii][jj]);
        }

        #pragma unroll
        for (int ii = 0; ii < 4; ii++) {
            int i = i0 + ii;
            if (i < K2) {
                #pragma unroll
                for (int jj = 0; jj < 4; jj++) {
                    int j = j0 + jj;
                    if (j < K2) {
                        int idx = i * K2 + j;
                        S[(h * K2 + i) * S_STR + j] =
                            acc[ii][jj] + rpb[rp[idx] * NH + h] + maskb[idx];
                    }
                }
            }
        }
    }
    __syncthreads();

    // ---------------- Phase 4: softmax, warp per row ----------------
    {
        int warp = tid >> 5, lane = tid & 31;
        for (int row = warp; row < NH * K2; row += NT / 32) {
            float* srow = S + row * S_STR;
            float v0 = srow[lane];
            float v1 = (lane < 17) ? srow[32 + lane] : -1e30f;
            float m = fmaxf(v0, v1);
            #pragma unroll
            for (int o = 16; o; o >>= 1) m = fmaxf(m, __shfl_xor_sync(~0u, m, o));
            float e0 = __expf(v0 - m);
            float e1 = (lane < 17) ? __expf(v1 - m) : 0.f;
            float sum = e0 + e1;
            #pragma unroll
            for (int o = 16; o; o >>= 1) sum += __shfl_xor_sync(~0u, sum, o);
            float inv = __fdividef(1.f, sum);
            srow[lane] = e0 * inv;
            if (lane < 17) srow[32 + lane] = e1 * inv;
        }
    }
    __syncthreads();

    // ---------------- Phase 5: V[i][he] = bott[i]*(S@Y^T + Bw), 4i x 4e tiles (312) ----------------
    if (tid < 312) {
        const int h   = tid / 104;
        const int rem = tid - h * 104;
        const int e0  = (rem / 13) * 4;
        const int i0  = (rem % 13) * 4;
        const float* ybase = P + (192 + h * 32 + e0) * P_STR;
        const float* sbase = S + (h * K2 + i0) * S_STR;

        float acc[4][4];
        #pragma unroll
        for (int ii = 0; ii < 4; ii++)
            #pragma unroll
            for (int ee = 0; ee < 4; ee++) acc[ii][ee] = 0.f;

        #pragma unroll 2
        for (int j0 = 0; j0 < 52; j0 += 4) {
            float4 sv[4], yv[4];
            #pragma unroll
            for (int ii = 0; ii < 4; ii++) sv[ii] = *(const float4*)&sbase[ii * S_STR + j0];
            #pragma unroll
            for (int ee = 0; ee < 4; ee++) yv[ee] = *(const float4*)&ybase[ee * P_STR + j0];
            #pragma unroll
            for (int ii = 0; ii < 4; ii++)
                #pragma unroll
                for (int ee = 0; ee < 4; ee++)
                    acc[ii][ee] = dot4(sv[ii], yv[ee], acc[ii][ee]);
        }

        float4 bw4 = *(const float4*)&Bw[h * 32 + e0];
        #pragma unroll
        for (int ii = 0; ii < 4; ii++) {
            int i = i0 + ii;
            if (i < K2) {
                float bt = bott[i];
                float4 o = make_float4(bt * (acc[ii][0] + bw4.x),
                                       bt * (acc[ii][1] + bw4.y),
                                       bt * (acc[ii][2] + bw4.z),
                                       bt * (acc[ii][3] + bw4.w));
                *(float4*)&V[i * V_STR + h * 32 + e0] = o;
            }
        }
    }
    __syncthreads();

    // ---------------- Phase 6: output projection, 4d x 4i tiles (312) ----------------
    float* og = out + (size_t)b * (K2 * DIMC);
    if (tid < 312) {
        const int d0 = (tid / 13) * 4;
        const int i0 = (tid % 13) * 4;

        float4 pb4 = *(const float4*)&pb[d0];
        float acc[4][4];
        #pragma unroll
        for (int ii = 0; ii < 4; ii++) {
            acc[ii][0] = pb4.x; acc[ii][1] = pb4.y; acc[ii][2] = pb4.z; acc[ii][3] = pb4.w;
        }

        #pragma unroll 2
        for (int c0 = 0; c0 < DIMC; c0 += 4) {
            float4 vv[4], wv[4];
            #pragma unroll
            for (int ii = 0; ii < 4; ii++) vv[ii] = *(const float4*)&V[(i0 + ii) * V_STR + c0];
            #pragma unroll
            for (int dd = 0; dd < 4; dd++) wv[dd] = *(const float4*)&pw[(d0 + dd) * 96 + c0];
            #pragma unroll
            for (int ii = 0; ii < 4; ii++)
                #pragma unroll
                for (int dd = 0; dd < 4; dd++)
                    acc[ii][dd] = dot4(vv[ii], wv[dd], acc[ii][dd]);
        }

        #pragma unroll
        for (int ii = 0; ii < 4; ii++) {
            int i = i0 + ii;
            if (i < K2) {
                float4 o = make_float4(acc[ii][0], acc[ii][1], acc[ii][2], acc[ii][3]);
                *(float4*)&og[i * DIMC + d0] = o;
            }
        }
    }
}

extern "C" void kernel_launch(void* const* d_in, const int* in_sizes, int n_in,
                              void* d_out, int out_size) {
    const float* x    = (const float*)d_in[0];
    const float* mask = (const float*)d_in[1];
    const float* qk_w = (const float*)d_in[2];
    const float* qk_b = (const float*)d_in[3];
    const float* rpb  = (const float*)d_in[4];
    const float* botw = (const float*)d_in[5];
    const float* botb = (const float*)d_in[6];
    const float* Gw   = (const float*)d_in[7];
    const float* Bw   = (const float*)d_in[8];
    const float* pw   = (const float*)d_in[9];
    const float* pb   = (const float*)d_in[10];
    const int*   rp   = (const int*)d_in[11];

    const int BW = in_sizes[0] / (K2 * DIMC);        // 128
    const int nW = in_sizes[1] / (K2 * K2);          // 64

    size_t smem = SMEM_FLOATS * sizeof(float);
    cudaFuncSetAttribute(gwa_kernel, cudaFuncAttributeMaxDynamicSharedMemorySize, (int)smem);
    gwa_kernel<<<BW, NT, smem>>>(x, mask, qk_w, qk_b, rpb, botw, botb,
                                 Gw, Bw, pw, pb, rp, (float*)d_out, nW);
}

// round 3
// speedup vs baseline: 5.0189x; 1.3722x over previous
#include <cuda_runtime.h>

#define K2   49
#define KP   56      // padded token dim
#define NH   3
#define DIMC 96
#define NT   512

// ---- shared memory layout (floats) ----
#define XT_STR  60
#define XT_OFF  0                               // xT[96][60]  xT[c][j]
#define GWT_OFF (XT_OFF + 96 * XT_STR)          // 5760
#define GWT_STR 100                             // GwT[96][100] GwT[he][c]
#define P_OFF   (GWT_OFF + 96 * GWT_STR)        // 15360
#define P_STR   60                              // P[288][60]: Q rows 0..95, K 96..191, Y^T 192..287
#define S_OFF   (P_OFF + 288 * P_STR)           // 32640
#define S_STR   60                              // S[147][60]
#define VT_OFF  (S_OFF + 147 * S_STR)           // 41460
#define VT_STR  60                              // VT[96][60]  VT[he][i]
#define BOTT_OFF (VT_OFF + 96 * VT_STR)         // 47220
#define SMEM_FLOATS (BOTT_OFF + 64)             // 47284 floats = 189136 B

__device__ __forceinline__ float dot4(float4 a, float4 b, float acc) {
    acc = fmaf(a.x, b.x, acc);
    acc = fmaf(a.y, b.y, acc);
    acc = fmaf(a.z, b.z, acc);
    acc = fmaf(a.w, b.w, acc);
    return acc;
}
__device__ __forceinline__ float fcomp(float4 v, int k) {
    return k == 0 ? v.x : (k == 1 ? v.y : (k == 2 ? v.z : v.w));
}

__global__ __launch_bounds__(NT, 1)
void gwa_kernel(const float* __restrict__ x,    const float* __restrict__ mask,
                const float* __restrict__ qk_w, const float* __restrict__ qk_b,
                const float* __restrict__ rpb,  const float* __restrict__ botw,
                const float* __restrict__ botb, const float* __restrict__ Gw,
                const float* __restrict__ Bw,   const float* __restrict__ pw,
                const float* __restrict__ pb,   const int*   __restrict__ rp,
                float* __restrict__ out, int nW)
{
    extern __shared__ float sm[];
    float* xT   = sm + XT_OFF;    // [96][60]  xT[c][j], cols 49..55 zero
    float* GwT  = sm + GWT_OFF;   // [96][100] GwT[he][c]
    float* P    = sm + P_OFF;     // [288][60]
    float* S    = sm + S_OFF;     // [147][60]
    float* VT   = sm + VT_OFF;    // [96][60]
    float* bott = sm + BOTT_OFF;  // [56]

    const int b   = blockIdx.x;
    const int tid = threadIdx.x;
    const float* xg = x + (size_t)b * (K2 * DIMC);

    // ---------------- Phase 1: stage xT (transposed), GwT, bott ----------------
    for (int i = tid; i < K2 * DIMC; i += NT) {          // transpose store: lanes vary c -> ok banks
        int j = i / DIMC, c = i - j * DIMC;
        xT[c * XT_STR + j] = xg[i];
    }
    for (int i = tid; i < DIMC * (KP - K2); i += NT) {   // zero xT cols 49..55
        int c = i / (KP - K2), j = K2 + (i % (KP - K2));
        xT[c * XT_STR + j] = 0.f;
    }
    for (int i = tid; i < DIMC * DIMC; i += NT) {        // GwT[he][c] = Gw[c*96+he]
        int c = i / DIMC, he = i - c * DIMC;
        GwT[he * GWT_STR + c] = Gw[i];
    }
    if (tid < KP) {
        float acc = 0.f;
        if (tid < K2) {
            const float4* xr  = (const float4*)(xg + tid * DIMC);
            const float4* bw4 = (const float4*)botw;
            acc = botb[0];
            #pragma unroll 6
            for (int c4 = 0; c4 < 24; c4++) acc = dot4(xr[c4], bw4[c4], acc);
        }
        bott[tid] = acc;
    }
    __syncthreads();

    // ---------------- Phase 2: fused Q/K/Y projection, 8r x 4j tiles (504) ----------------
    const float SCALE = 0.17677669529663687f;  // 32^-0.5
    if (tid < 504) {
        const int rt = tid / 14;          // r-tile slow
        const int jt = tid - rt * 14;     // j-tile fast (lanes vary j0 -> contiguous dim)
        const int r0 = rt * 8;
        const int j0 = jt * 4;
        const bool isQK = (r0 < 192);
        const float* wbase = isQK ? (qk_w + r0 * 96) : (GwT + (r0 - 192) * GWT_STR);
        const int    wstr  = isQK ? 96 : GWT_STR;

        float acc[8][4];
        #pragma unroll
        for (int a = 0; a < 8; a++) {
            float bv = isQK ? qk_b[r0 + a] : 0.f;
            #pragma unroll
            for (int u = 0; u < 4; u++) acc[a][u] = bv;
        }

        #pragma unroll 2
        for (int c0 = 0; c0 < DIMC; c0 += 4) {
            float4 xv[4];
            #pragma unroll
            for (int cc = 0; cc < 4; cc++)
                xv[cc] = *(const float4*)&xT[(c0 + cc) * XT_STR + j0];
            #pragma unroll
            for (int a = 0; a < 8; a++) {
                float4 wv = *(const float4*)&wbase[a * wstr + c0];
                #pragma unroll
                for (int cc = 0; cc < 4; cc++) {
                    float w = fcomp(wv, cc);
                    acc[a][0] = fmaf(w, fcomp(xv[cc], 0), acc[a][0]);
                    acc[a][1] = fmaf(w, fcomp(xv[cc], 1), acc[a][1]);
                    acc[a][2] = fmaf(w, fcomp(xv[cc], 2), acc[a][2]);
                    acc[a][3] = fmaf(w, fcomp(xv[cc], 3), acc[a][3]);
                }
            }
        }

        const float s = (r0 < 96) ? SCALE : 1.f;
        #pragma unroll
        for (int a = 0; a < 8; a++) {
            float4 o = make_float4(acc[a][0] * s, acc[a][1] * s, acc[a][2] * s, acc[a][3] * s);
            *(float4*)&P[(r0 + a) * P_STR + j0] = o;
        }
    }
    __syncthreads();

    // ---------------- Phase 3: logits 4i x 8j tiles (273) + bias/mask ----------------
    const float* maskb = mask + (size_t)(b % nW) * (K2 * K2);
    if (tid < 273) {
        const int h   = tid / 91;
        const int rem = tid - h * 91;
        const int it  = rem / 7;
        const int jt  = rem - it * 7;     // j-tile fast
        const int i0  = it * 4;
        const int j0  = jt * 8;
        const float* qbase = P + (h * 32) * P_STR + i0;
        const float* kbase = P + (96 + h * 32) * P_STR + j0;

        float acc[4][8];
        #pragma unroll
        for (int ii = 0; ii < 4; ii++)
            #pragma unroll
            for (int jj = 0; jj < 8; jj++) acc[ii][jj] = 0.f;

        #pragma unroll 2
        for (int e = 0; e < 32; e++) {
            float4 qv  = *(const float4*)&qbase[e * P_STR];
            float4 kv0 = *(const float4*)&kbase[e * P_STR];
            float4 kv1 = *(const float4*)&kbase[e * P_STR + 4];
            #pragma unroll
            for (int ii = 0; ii < 4; ii++) {
                float q = fcomp(qv, ii);
                acc[ii][0] = fmaf(q, kv0.x, acc[ii][0]);
                acc[ii][1] = fmaf(q, kv0.y, acc[ii][1]);
                acc[ii][2] = fmaf(q, kv0.z, acc[ii][2]);
                acc[ii][3] = fmaf(q, kv0.w, acc[ii][3]);
                acc[ii][4] = fmaf(q, kv1.x, acc[ii][4]);
                acc[ii][5] = fmaf(q, kv1.y, acc[ii][5]);
                acc[ii][6] = fmaf(q, kv1.z, acc[ii][6]);
                acc[ii][7] = fmaf(q, kv1.w, acc[ii][7]);
            }
        }

        #pragma unroll
        for (int ii = 0; ii < 4; ii++) {
            int i = i0 + ii;
            if (i < K2) {
                float* srow = S + (h * K2 + i) * S_STR;
                #pragma unroll
                for (int jj = 0; jj < 8; jj++) {
                    int j = j0 + jj;
                    float v = acc[ii][jj];
                    if (j < K2) {
                        int idx = i * K2 + j;
                        v += rpb[rp[idx] * NH + h] + maskb[idx];
                    }
                    srow[j] = v;
                }
            }
        }
    }
    __syncthreads();

    // ---------------- Phase 4: softmax, warp per row ----------------
    {
        int warp = tid >> 5, lane = tid & 31;
        for (int row = warp; row < NH * K2; row += NT / 32) {
            float* srow = S + row * S_STR;
            float v0 = srow[lane];
            float v1 = (lane < 17) ? srow[32 + lane] : -1e30f;
            float m = fmaxf(v0, v1);
            #pragma unroll
            for (int o = 16; o; o >>= 1) m = fmaxf(m, __shfl_xor_sync(~0u, m, o));
            float e0 = __expf(v0 - m);
            float e1 = (lane < 17) ? __expf(v1 - m) : 0.f;
            float sum = e0 + e1;
            #pragma unroll
            for (int o = 16; o; o >>= 1) sum += __shfl_xor_sync(~0u, sum, o);
            float inv = __fdividef(1.f, sum);
            srow[lane] = e0 * inv;
            if (lane < 17) srow[32 + lane] = e1 * inv;
        }
    }
    __syncthreads();

    // ---------------- Phase 5: VT[he][i] = bott[i]*(S@Y^T + Bw), 4i x 8e tiles (156) ----------------
    if (tid < 156) {
        const int h   = tid / 52;
        const int rem = tid - h * 52;
        const int et  = rem / 13;
        const int it  = rem - et * 13;    // i-tile fast
        const int i0  = it * 4;
        const int e0  = et * 8;
        const float* sbase = S + (h * K2 + i0) * S_STR;
        const float* ybase = P + (192 + h * 32 + e0) * P_STR;

        float acc[4][8];
        #pragma unroll
        for (int ii = 0; ii < 4; ii++)
            #pragma unroll
            for (int ee = 0; ee < 8; ee++) acc[ii][ee] = 0.f;

        #pragma unroll 2
        for (int j0 = 0; j0 < KP; j0 += 4) {
            float4 sv[4], yv[8];
            #pragma unroll
            for (int ii = 0; ii < 4; ii++) sv[ii] = *(const float4*)&sbase[ii * S_STR + j0];
            #pragma unroll
            for (int ee = 0; ee < 8; ee++) yv[ee] = *(const float4*)&ybase[ee * P_STR + j0];
            #pragma unroll
            for (int ii = 0; ii < 4; ii++)
                #pragma unroll
                for (int ee = 0; ee < 8; ee++)
                    acc[ii][ee] = dot4(sv[ii], yv[ee], acc[ii][ee]);
        }

        float bt[4];
        #pragma unroll
        for (int ii = 0; ii < 4; ii++) bt[ii] = bott[i0 + ii];
        #pragma unroll
        for (int ee = 0; ee < 8; ee++) {
            float bw = Bw[h * 32 + e0 + ee];
            float4 o = make_float4(bt[0] * (acc[0][ee] + bw),
                                   bt[1] * (acc[1][ee] + bw),
                                   bt[2] * (acc[2][ee] + bw),
                                   bt[3] * (acc[3][ee] + bw));
            *(float4*)&VT[(h * 32 + e0 + ee) * VT_STR + i0] = o;
        }
    }
    __syncthreads();

    // ---------------- Phase 6: out[i][d] = sum_he VT[he][i]*pw[d][he], 4i x 8d tiles (156) ----------------
    float* og = out + (size_t)b * (K2 * DIMC);
    if (tid < 156) {
        const int dt = tid / 13;
        const int it = tid - dt * 13;     // i-tile fast
        const int d0 = dt * 8;
        const int i0 = it * 4;

        float acc[4][8];
        #pragma unroll
        for (int dd = 0; dd < 8; dd++) {
            float bv = pb[d0 + dd];
            #pragma unroll
            for (int ii = 0; ii < 4; ii++) acc[ii][dd] = bv;
        }

        #pragma unroll 2
        for (int c0 = 0; c0 < DIMC; c0 += 4) {
            float4 vv[4], wv[8];
            #pragma unroll
            for (int cc = 0; cc < 4; cc++) vv[cc] = *(const float4*)&VT[(c0 + cc) * VT_STR + i0];
            #pragma unroll
            for (int dd = 0; dd < 8; dd++) wv[dd] = *(const float4*)&pw[(d0 + dd) * 96 + c0];
            #pragma unroll
            for (int cc = 0; cc < 4; cc++)
                #pragma unroll
                for (int dd = 0; dd < 8; dd++) {
                    float w = fcomp(wv[dd], cc);
                    acc[0][dd] = fmaf(w, fcomp(vv[cc], 0), acc[0][dd]);
                    acc[1][dd] = fmaf(w, fcomp(vv[cc], 1), acc[1][dd]);
                    acc[2][dd] = fmaf(w, fcomp(vv[cc], 2), acc[2][dd]);
                    acc[3][dd] = fmaf(w, fcomp(vv[cc], 3), acc[3][dd]);
                }
        }

        #pragma unroll
        for (int ii = 0; ii < 4; ii++) {
            int i = i0 + ii;
            if (i < K2) {
                float4 o0 = make_float4(acc[ii][0], acc[ii][1], acc[ii][2], acc[ii][3]);
                float4 o1 = make_float4(acc[ii][4], acc[ii][5], acc[ii][6], acc[ii][7]);
                *(float4*)&og[i * DIMC + d0]     = o0;
                *(float4*)&og[i * DIMC + d0 + 4] = o1;
            }
        }
    }
}

extern "C" void kernel_launch(void* const* d_in, const int* in_sizes, int n_in,
                              void* d_out, int out_size) {
    const float* x    = (const float*)d_in[0];
    const float* mask = (const float*)d_in[1];
    const float* qk_w = (const float*)d_in[2];
    const float* qk_b = (const float*)d_in[3];
    const float* rpb  = (const float*)d_in[4];
    const float* botw = (const float*)d_in[5];
    const float* botb = (const float*)d_in[6];
    const float* Gw   = (const float*)d_in[7];
    const float* Bw   = (const float*)d_in[8];
    const float* pw   = (const float*)d_in[9];
    const float* pb   = (const float*)d_in[10];
    const int*   rp   = (const int*)d_in[11];

    const int BW = in_sizes[0] / (K2 * DIMC);        // 128
    const int nW = in_sizes[1] / (K2 * K2);          // 64

    size_t smem = SMEM_FLOATS * sizeof(float);
    cudaFuncSetAttribute(gwa_kernel, cudaFuncAttributeMaxDynamicSharedMemorySize, (int)smem);
    gwa_kernel<<<BW, NT, smem>>>(x, mask, qk_w, qk_b, rpb, botw, botb,
                                 Gw, Bw, pw, pb, rp, (float*)d_out, nW);
}

// round 5
// speedup vs baseline: 5.2405x; 1.0442x over previous
#include <cuda_runtime.h>

#define K2   49
#define KP   56      // padded token dim
#define NH   3
#define DIMC 96
#define NT   512

// ---- shared memory layout (floats) ----
#define XT_STR  60
#define XT_OFF  0                               // xT[96][60]  xT[c][j]
#define GWT_OFF (XT_OFF + 96 * XT_STR)          // 5760
#define GWT_STR 100                             // GwT[96][100] GwT[he][c]
#define P_OFF   (GWT_OFF + 96 * GWT_STR)        // 15360
#define P_STR   60                              // P[288][60]: Q rows 0..95, K 96..191, Y^T 192..287
#define S_OFF   (P_OFF + 288 * P_STR)           // 32640
#define S_STR   60                              // S[147][60]
#define VT_OFF  (S_OFF + 147 * S_STR)           // 41460
#define VT_STR  60                              // VT[96][60]  VT[he][i]
#define BOTT_OFF (VT_OFF + 96 * VT_STR)         // 47220
#define SMEM_FLOATS (BOTT_OFF + 64)             // 47284 floats = 189136 B

__device__ __forceinline__ float dot4(float4 a, float4 b, float acc) {
    acc = fmaf(a.x, b.x, acc);
    acc = fmaf(a.y, b.y, acc);
    acc = fmaf(a.z, b.z, acc);
    acc = fmaf(a.w, b.w, acc);
    return acc;
}
__device__ __forceinline__ float fcomp(float4 v, int k) {
    return k == 0 ? v.x : (k == 1 ? v.y : (k == 2 ? v.z : v.w));
}

// packed 2xfp32 fma: d = a*b + c (Blackwell FFMA2; same rounding as scalar fmaf)
__device__ __forceinline__ float2 ffma2(float2 a, float2 b, float2 c) {
    float2 d;
    asm("{\n\t"
        ".reg .b64 ra, rb, rc, rd;\n\t"
        "mov.b64 ra, {%2,%3};\n\t"
        "mov.b64 rb, {%4,%5};\n\t"
        "mov.b64 rc, {%6,%7};\n\t"
        "fma.rn.f32x2 rd, ra, rb, rc;\n\t"
        "mov.b64 {%0,%1}, rd;\n\t"
        "}"
        : "=f"(d.x), "=f"(d.y)
        : "f"(a.x), "f"(a.y), "f"(b.x), "f"(b.y), "f"(c.x), "f"(c.y));
    return d;
}

__global__ __launch_bounds__(NT, 1)
void gwa_kernel(const float* __restrict__ x,    const float* __restrict__ mask,
                const float* __restrict__ qk_w, const float* __restrict__ qk_b,
                const float* __restrict__ rpb,  const float* __restrict__ botw,
                const float* __restrict__ botb, const float* __restrict__ Gw,
                const float* __restrict__ Bw,   const float* __restrict__ pw,
                const float* __restrict__ pb,   const int*   __restrict__ rp,
                float* __restrict__ out, int nW)
{
    extern __shared__ float sm[];
    float* xT   = sm + XT_OFF;    // [96][60]  xT[c][j], cols 49..55 zero
    float* GwT  = sm + GWT_OFF;   // [96][100] GwT[he][c]
    float* P    = sm + P_OFF;     // [288][60]
    float* S    = sm + S_OFF;     // [147][60]
    float* VT   = sm + VT_OFF;    // [96][60]
    float* bott = sm + BOTT_OFF;  // [56]

    const int b   = blockIdx.x;
    const int tid = threadIdx.x;
    const float* xg = x + (size_t)b * (K2 * DIMC);

    // ---------------- Phase 1: stage xT (transposed), GwT, bott ----------------
    for (int i = tid; i < K2 * DIMC; i += NT) {
        int j = i / DIMC, c = i - j * DIMC;
        xT[c * XT_STR + j] = xg[i];
    }
    for (int i = tid; i < DIMC * (KP - K2); i += NT) {   // zero xT cols 49..55
        int c = i / (KP - K2), j = K2 + (i % (KP - K2));
        xT[c * XT_STR + j] = 0.f;
    }
    for (int i = tid; i < DIMC * DIMC; i += NT) {        // GwT[he][c] = Gw[c*96+he]
        int c = i / DIMC, he = i - c * DIMC;
        GwT[he * GWT_STR + c] = Gw[i];
    }
    if (tid < KP) {
        float acc = 0.f;
        if (tid < K2) {
            const float4* xr  = (const float4*)(xg + tid * DIMC);
            const float4* bw4 = (const float4*)botw;
            acc = botb[0];
            #pragma unroll 6
            for (int c4 = 0; c4 < 24; c4++) acc = dot4(xr[c4], bw4[c4], acc);
        }
        bott[tid] = acc;
    }
    __syncthreads();

    // ---------------- Phase 2: fused Q/K/Y projection, 8r x 4j tiles (504) ----------------
    const float SCALE = 0.17677669529663687f;  // 32^-0.5
    if (tid < 504) {
        const int rt = tid / 14;
        const int jt = tid - rt * 14;
        const int r0 = rt * 8;
        const int j0 = jt * 4;
        const bool isQK = (r0 < 192);
        const float* wbase = isQK ? (qk_w + r0 * 96) : (GwT + (r0 - 192) * GWT_STR);
        const int    wstr  = isQK ? 96 : GWT_STR;

        float2 acc[8][2];   // pairs along j
        #pragma unroll
        for (int a = 0; a < 8; a++) {
            float bv = isQK ? qk_b[r0 + a] : 0.f;
            acc[a][0] = make_float2(bv, bv);
            acc[a][1] = make_float2(bv, bv);
        }

        #pragma unroll 2
        for (int c0 = 0; c0 < DIMC; c0 += 4) {
            float2 xlo[4], xhi[4];
            #pragma unroll
            for (int cc = 0; cc < 4; cc++) {
                float4 xv = *(const float4*)&xT[(c0 + cc) * XT_STR + j0];
                xlo[cc] = make_float2(xv.x, xv.y);
                xhi[cc] = make_float2(xv.z, xv.w);
            }
            #pragma unroll
            for (int a = 0; a < 8; a++) {
                float4 wv = *(const float4*)&wbase[a * wstr + c0];
                #pragma unroll
                for (int cc = 0; cc < 4; cc++) {
                    float w = fcomp(wv, cc);
                    float2 w2 = make_float2(w, w);
                    acc[a][0] = ffma2(w2, xlo[cc], acc[a][0]);
                    acc[a][1] = ffma2(w2, xhi[cc], acc[a][1]);
                }
            }
        }

        const float s = (r0 < 96) ? SCALE : 1.f;
        #pragma unroll
        for (int a = 0; a < 8; a++) {
            float4 o = make_float4(acc[a][0].x * s, acc[a][0].y * s,
                                   acc[a][1].x * s, acc[a][1].y * s);
            *(float4*)&P[(r0 + a) * P_STR + j0] = o;
        }
    }
    __syncthreads();

    // ---------------- Phase 3: logits 4i x 8j tiles (273) + bias/mask ----------------
    const float* maskb = mask + (size_t)(b % nW) * (K2 * K2);
    if (tid < 273) {
        const int h   = tid / 91;
        const int rem = tid - h * 91;
        const int it  = rem / 7;
        const int jt  = rem - it * 7;
        const int i0  = it * 4;
        const int j0  = jt * 8;
        const float* qbase = P + (h * 32) * P_STR + i0;
        const float* kbase = P + (96 + h * 32) * P_STR + j0;

        float2 acc[4][4];   // 4 i x 4 j-pairs
        #pragma unroll
        for (int ii = 0; ii < 4; ii++)
            #pragma unroll
            for (int jp = 0; jp < 4; jp++) acc[ii][jp] = make_float2(0.f, 0.f);

        #pragma unroll 2
        for (int e = 0; e < 32; e++) {
            float4 qv  = *(const float4*)&qbase[e * P_STR];
            float4 kv0 = *(const float4*)&kbase[e * P_STR];
            float4 kv1 = *(const float4*)&kbase[e * P_STR + 4];
            float2 kp[4] = { make_float2(kv0.x, kv0.y), make_float2(kv0.z, kv0.w),
                             make_float2(kv1.x, kv1.y), make_float2(kv1.z, kv1.w) };
            #pragma unroll
            for (int ii = 0; ii < 4; ii++) {
                float q = fcomp(qv, ii);
                float2 q2 = make_float2(q, q);
                #pragma unroll
                for (int jp = 0; jp < 4; jp++)
                    acc[ii][jp] = ffma2(q2, kp[jp], acc[ii][jp]);
            }
        }

        #pragma unroll
        for (int ii = 0; ii < 4; ii++) {
            int i = i0 + ii;
            if (i < K2) {
                float* srow = S + (h * K2 + i) * S_STR;
                float av[8] = { acc[ii][0].x, acc[ii][0].y, acc[ii][1].x, acc[ii][1].y,
                                acc[ii][2].x, acc[ii][2].y, acc[ii][3].x, acc[ii][3].y };
                #pragma unroll
                for (int jj = 0; jj < 8; jj++) {
                    int j = j0 + jj;
                    float v = av[jj];
                    if (j < K2) {
                        int idx = i * K2 + j;
                        v += rpb[rp[idx] * NH + h] + maskb[idx];
                    }
                    srow[j] = v;
                }
            }
        }
    }
    __syncthreads();

    // ---------------- Phase 4: softmax, warp per row ----------------
    {
        int warp = tid >> 5, lane = tid & 31;
        for (int row = warp; row < NH * K2; row += NT / 32) {
            float* srow = S + row * S_STR;
            float v0 = srow[lane];
            float v1 = (lane < 17) ? srow[32 + lane] : -1e30f;
            float m = fmaxf(v0, v1);
            #pragma unroll
            for (int o = 16; o; o >>= 1) m = fmaxf(m, __shfl_xor_sync(~0u, m, o));
            float e0 = __expf(v0 - m);
            float e1 = (lane < 17) ? __expf(v1 - m) : 0.f;
            float sum = e0 + e1;
            #pragma unroll
            for (int o = 16; o; o >>= 1) sum += __shfl_xor_sync(~0u, sum, o);
            float inv = __fdividef(1.f, sum);
            srow[lane] = e0 * inv;
            if (lane < 17) srow[32 + lane] = e1 * inv;
        }
    }
    __syncthreads();

    // ---------------- Phase 5: VT[he][i] = bott[i]*(S@Y^T + Bw), 4i x 8e tiles (156) ----------------
    if (tid < 156) {
        const int h   = tid / 52;
        const int rem = tid - h * 52;
        const int et  = rem / 13;
        const int it  = rem - et * 13;
        const int i0  = it * 4;
        const int e0  = et * 8;
        const float* sbase = S + (h * K2 + i0) * S_STR;
        const float* ybase = P + (192 + h * 32 + e0) * P_STR;

        float2 acc[4][8];   // j-pair partial sums, zero packing overhead
        #pragma unroll
        for (int ii = 0; ii < 4; ii++)
            #pragma unroll
            for (int ee = 0; ee < 8; ee++) acc[ii][ee] = make_float2(0.f, 0.f);

        #pragma unroll 2
        for (int j0 = 0; j0 < KP; j0 += 4) {
            float2 sp[4][2], yp[8][2];
            #pragma unroll
            for (int ii = 0; ii < 4; ii++) {
                float4 sv = *(const float4*)&sbase[ii * S_STR + j0];
                sp[ii][0] = make_float2(sv.x, sv.y);
                sp[ii][1] = make_float2(sv.z, sv.w);
            }
            #pragma unroll
            for (int ee = 0; ee < 8; ee++) {
                float4 yv = *(const float4*)&ybase[ee * P_STR + j0];
                yp[ee][0] = make_float2(yv.x, yv.y);
                yp[ee][1] = make_float2(yv.z, yv.w);
            }
            #pragma unroll
            for (int ii = 0; ii < 4; ii++)
                #pragma unroll
                for (int ee = 0; ee < 8; ee++) {
                    acc[ii][ee] = ffma2(sp[ii][0], yp[ee][0], acc[ii][ee]);
                    acc[ii][ee] = ffma2(sp[ii][1], yp[ee][1], acc[ii][ee]);
                }
        }

        float bt[4];
        #pragma unroll
        for (int ii = 0; ii < 4; ii++) bt[ii] = bott[i0 + ii];
        #pragma unroll
        for (int ee = 0; ee < 8; ee++) {
            float bw = Bw[h * 32 + e0 + ee];
            float4 o = make_float4(bt[0] * (acc[0][ee].x + acc[0][ee].y + bw),
                                   bt[1] * (acc[1][ee].x + acc[1][ee].y + bw),
                                   bt[2] * (acc[2][ee].x + acc[2][ee].y + bw),
                                   bt[3] * (acc[3][ee].x + acc[3][ee].y + bw));
            *(float4*)&VT[(h * 32 + e0 + ee) * VT_STR + i0] = o;
        }
    }
    __syncthreads();

    // ---------------- Phase 6: out[i][d] = sum_he VT[he][i]*pw[d][he], 4i x 8d tiles (156) ----------------
    float* og = out + (size_t)b * (K2 * DIMC);
    if (tid < 156) {
        const int dt = tid / 13;
        const int it = tid - dt * 13;
        const int d0 = dt * 8;
        const int i0 = it * 4;

        float2 acc[2][8];   // 2 i-pairs x 8 d
        #pragma unroll
        for (int dd = 0; dd < 8; dd++) {
            float bv = pb[d0 + dd];
            acc[0][dd] = make_float2(bv, bv);
            acc[1][dd] = make_float2(bv, bv);
        }

        #pragma unroll 2
        for (int c0 = 0; c0 < DIMC; c0 += 4) {
            float2 vlo[4], vhi[4];
            #pragma unroll
            for (int cc = 0; cc < 4; cc++) {
                float4 vv = *(const float4*)&VT[(c0 + cc) * VT_STR + i0];
                vlo[cc] = make_float2(vv.x, vv.y);
                vhi[cc] = make_float2(vv.z, vv.w);
            }
            #pragma unroll
            for (int dd = 0; dd < 8; dd++) {
                float4 wv = *(const float4*)&pw[(d0 + dd) * 96 + c0];
                #pragma unroll
                for (int cc = 0; cc < 4; cc++) {
                    float w = fcomp(wv, cc);
                    float2 w2 = make_float2(w, w);
                    acc[0][dd] = ffma2(w2, vlo[cc], acc[0][dd]);
                    acc[1][dd] = ffma2(w2, vhi[cc], acc[1][dd]);
                }
            }
        }

        #pragma unroll
        for (int ip = 0; ip < 2; ip++) {
            #pragma unroll
            for (int half = 0; half < 2; half++) {
                int i = i0 + ip * 2 + half;
                if (i < K2) {
                    float4 o0, o1;
                    if (half == 0) {
                        o0 = make_float4(acc[ip][0].x, acc[ip][1].x, acc[ip][2].x, acc[ip][3].x);
                        o1 = make_float4(acc[ip][4].x, acc[ip][5].x, acc[ip][6].x, acc[ip][7].x);
                    } else {
                        o0 = make_float4(acc[ip][0].y, acc[ip][1].y, acc[ip][2].y, acc[ip][3].y);
                        o1 = make_float4(acc[ip][4].y, acc[ip][5].y, acc[ip][6].y, acc[ip][7].y);
                    }
                    *(float4*)&og[i * DIMC + d0]     = o0;
                    *(float4*)&og[i * DIMC + d0 + 4] = o1;
                }
            }
        }
    }
}

extern "C" void kernel_launch(void* const* d_in, const int* in_sizes, int n_in,
                              void* d_out, int out_size) {
    const float* x    = (const float*)d_in[0];
    const float* mask = (const float*)d_in[1];
    const float* qk_w = (const float*)d_in[2];
    const float* qk_b = (const float*)d_in[3];
    const float* rpb  = (const float*)d_in[4];
    const float* botw = (const float*)d_in[5];
    const float* botb = (const float*)d_in[6];
    const float* Gw   = (const float*)d_in[7];
    const float* Bw   = (const float*)d_in[8];
    const float* pw   = (const float*)d_in[9];
    const float* pb   = (const float*)d_in[10];
    const int*   rp   = (const int*)d_in[11];

    const int BW = in_sizes[0] / (K2 * DIMC);        // 128
    const int nW = in_sizes[1] / (K2 * K2);          // 64

    size_t smem = SMEM_FLOATS * sizeof(float);
    cudaFuncSetAttribute(gwa_kernel, cudaFuncAttributeMaxDynamicSharedMemorySize, (int)smem);
    gwa_kernel<<<BW, NT, smem>>>(x, mask, qk_w, qk_b, rpb, botw, botb,
                                 Gw, Bw, pw, pb, rp, (float*)d_out, nW);
}